// round 15
// baseline (speedup 1.0000x reference)
#include <cuda_runtime.h>
#include <cuda_bf16.h>
#include <cstdint>

#define BB 2
#define SS 2048
#define DD 1024
#define HH 16
#define DHD 64
#define NROWS (BB*SS)          // 4096
#define OUT_ELEMS (BB*SS*DD)   // 4194304
#define ATTN_ELEMS ((long long)HH*BB*SS*SS) // 134217728
#define K2 512                  // DD/2 packed bf16x2 words per row

// ---------------- scratch (device globals: allowed) ----------------
__device__ float g_q[NROWS * DD];
__device__ float g_k[NROWS * DD];
__device__ float g_v[NROWS * DD];
__device__ float g_concat[NROWS * DD];

// bf16 hi/lo split operands (packed pairs along k)
__device__ uint32_t g_ah[3][NROWS * K2];   // query/key/value inputs
__device__ uint32_t g_al[3][NROWS * K2];
__device__ uint32_t g_bh[4][DD * K2];      // Wq,Wk,Wv,Wo (n-major [n][k2])
__device__ uint32_t g_bl[4][DD * K2];
__device__ uint32_t g_ch[NROWS * K2];      // concat split
__device__ uint32_t g_cl[NROWS * K2];

// =====================================================================
// mma.sync helpers (sm_80+ PTX; compiles on plain sm_103 target)
// =====================================================================
__device__ __forceinline__ uint32_t f2tf32(float f) {
    uint32_t r;
    asm("cvt.rn.tf32.f32 %0, %1;" : "=r"(r) : "f"(f));
    return r;
}
__device__ __forceinline__ void mma_tf32(float c[4], const uint32_t a[4],
                                         uint32_t b0, uint32_t b1) {
    asm volatile(
        "mma.sync.aligned.m16n8k8.row.col.f32.tf32.tf32.f32 "
        "{%0,%1,%2,%3}, {%4,%5,%6,%7}, {%8,%9}, {%0,%1,%2,%3};"
        : "+f"(c[0]), "+f"(c[1]), "+f"(c[2]), "+f"(c[3])
        : "r"(a[0]), "r"(a[1]), "r"(a[2]), "r"(a[3]), "r"(b0), "r"(b1));
}
__device__ __forceinline__ void mma_bf16(float c[4], const uint32_t a[4],
                                         uint32_t b0, uint32_t b1) {
    asm volatile(
        "mma.sync.aligned.m16n8k16.row.col.f32.bf16.bf16.f32 "
        "{%0,%1,%2,%3}, {%4,%5,%6,%7}, {%8,%9}, {%0,%1,%2,%3};"
        : "+f"(c[0]), "+f"(c[1]), "+f"(c[2]), "+f"(c[3])
        : "r"(a[0]), "r"(a[1]), "r"(a[2]), "r"(a[3]), "r"(b0), "r"(b1));
}

// split a float2 into packed bf16x2 hi + residual lo
__device__ __forceinline__ void split2(float2 v, uint32_t& hi, uint32_t& lo) {
    __nv_bfloat162 h = __floats2bfloat162_rn(v.x, v.y);
    float r0 = v.x - __low2float(h);
    float r1 = v.y - __high2float(h);
    __nv_bfloat162 l = __floats2bfloat162_rn(r0, r1);
    hi = *(uint32_t*)&h;
    lo = *(uint32_t*)&l;
}

// =====================================================================
// Split kernels (one-shot fp32 -> bf16 hi/lo packed pairs)
// =====================================================================
__global__ void split_in(const float* __restrict__ src, int which) {
    const int idx = blockIdx.x * 256 + threadIdx.x;           // over NROWS*K2
    float2 v = *(const float2*)&src[(size_t)idx * 2];
    split2(v, g_ah[which][idx], g_al[which][idx]);
}
__global__ void split_w(const float* __restrict__ W, int which) {
    const int idx = blockIdx.x * 256 + threadIdx.x;           // over DD*K2
    const int e  = idx & 63;
    const int k2 = (idx >> 6) & 511;
    const int h  = idx >> 15;
    float f0 = W[(size_t)((h << 10) + (k2 << 1)) * 64 + e];
    float f1 = W[(size_t)((h << 10) + (k2 << 1) + 1) * 64 + e];
    uint32_t hi, lo;
    split2(make_float2(f0, f1), hi, lo);
    const int n = (h << 6) + e;
    g_bh[which][(size_t)n * K2 + k2] = hi;
    g_bl[which][(size_t)n * K2 + k2] = lo;
}
__global__ void split_wo(const float* __restrict__ Wo) {
    const int idx = blockIdx.x * 256 + threadIdx.x;           // over DD*K2
    const int n = idx >> 9, k2 = idx & 511;
    float2 v = *(const float2*)&Wo[(size_t)n * DD + (k2 << 1)];
    split2(v, g_bh[3][idx], g_bl[3][idx]);
}
__global__ void split_cat() {
    const int idx = blockIdx.x * 256 + threadIdx.x;           // over NROWS*K2
    float2 v = *(const float2*)&g_concat[(size_t)idx * 2];
    split2(v, g_ch[idx], g_cl[idx]);
}

// =====================================================================
// 3xBF16 tensor-core GEMM: C[4096 x 1024] = A[4096 x 1024] * B^T-ish
// mode 0..2: proj q/k/v (C = g_q/g_k/g_v); mode 3: out (C = outp)
// Tile 128x64, BK=64 (32 k2), 8 warps as 4m x 2n (warp m32 x n32).
// =====================================================================
#define GST 36   // smem row stride in u32 (32 k2 padded: conflict-free frags)

__global__ __launch_bounds__(256, 2) void gemm_tc(int base_mode,
                                                  float* __restrict__ outp)
{
    extern __shared__ uint32_t smu[];
    uint32_t* Ah = smu;                     // 128*36
    uint32_t* Al = smu + 128 * GST;
    uint32_t* Bh = smu + 2 * 128 * GST;     // 64*36
    uint32_t* Bl = smu + 2 * 128 * GST + 64 * GST;

    const int mode = base_mode + blockIdx.z;
    const uint32_t *a_hi, *a_lo, *b_hi, *b_lo;
    float* C;
    if (mode < 3) {
        a_hi = g_ah[mode]; a_lo = g_al[mode];
        b_hi = g_bh[mode]; b_lo = g_bl[mode];
        C = (mode == 0) ? g_q : (mode == 1) ? g_k : g_v;
    } else {
        a_hi = g_ch; a_lo = g_cl;
        b_hi = g_bh[3]; b_lo = g_bl[3];
        C = outp;
    }

    const int tid  = threadIdx.x;
    const int wid  = tid >> 5, lane = tid & 31;
    const int g    = lane >> 2, tg = lane & 3;
    const int wm   = wid >> 1, wn = wid & 1;
    const int row0 = blockIdx.x << 7;
    const int n0   = blockIdx.y << 6;

    float acc[2][4][4] = {};

    for (int kt = 0; kt < 16; kt++) {
        const int k2o = kt << 5;
        #pragma unroll
        for (int i = 0; i < 4; i++) {                     // A: 128x32 u32
            const int idx = tid + (i << 8);
            const int r = idx >> 3, q = (idx & 7) << 2;
            *(uint4*)&Ah[r * GST + q] =
                *(const uint4*)&a_hi[(size_t)(row0 + r) * K2 + k2o + q];
            *(uint4*)&Al[r * GST + q] =
                *(const uint4*)&a_lo[(size_t)(row0 + r) * K2 + k2o + q];
        }
        #pragma unroll
        for (int i = 0; i < 2; i++) {                     // B: 64x32 u32
            const int idx = tid + (i << 8);
            const int r = idx >> 3, q = (idx & 7) << 2;
            *(uint4*)&Bh[r * GST + q] =
                *(const uint4*)&b_hi[(size_t)(n0 + r) * K2 + k2o + q];
            *(uint4*)&Bl[r * GST + q] =
                *(const uint4*)&b_lo[(size_t)(n0 + r) * K2 + k2o + q];
        }
        __syncthreads();

        #pragma unroll
        for (int s = 0; s < 4; s++) {                     // 4 x k16 steps
            const int ko = s << 3;
            uint32_t ah[2][4], al[2][4];
            #pragma unroll
            for (int mi = 0; mi < 2; mi++) {
                const int ar = ((wm << 5) + (mi << 4) + g) * GST + ko + tg;
                ah[mi][0] = Ah[ar];            ah[mi][1] = Ah[ar + 8 * GST];
                ah[mi][2] = Ah[ar + 4];        ah[mi][3] = Ah[ar + 8 * GST + 4];
                al[mi][0] = Al[ar];            al[mi][1] = Al[ar + 8 * GST];
                al[mi][2] = Al[ar + 4];        al[mi][3] = Al[ar + 8 * GST + 4];
            }
            #pragma unroll
            for (int ni = 0; ni < 4; ni++) {
                const int br = ((wn << 5) + (ni << 3) + g) * GST + ko + tg;
                const uint32_t bh0 = Bh[br], bh1 = Bh[br + 4];
                const uint32_t bl0 = Bl[br], bl1 = Bl[br + 4];
                #pragma unroll
                for (int mi = 0; mi < 2; mi++) {
                    mma_bf16(acc[mi][ni], ah[mi], bh0, bh1);
                    mma_bf16(acc[mi][ni], ah[mi], bl0, bl1);
                    mma_bf16(acc[mi][ni], al[mi], bh0, bh1);
                }
            }
        }
        __syncthreads();
    }

    #pragma unroll
    for (int mi = 0; mi < 2; mi++) {
        const int row = row0 + (wm << 5) + (mi << 4) + g;
        #pragma unroll
        for (int ni = 0; ni < 4; ni++) {
            const int col = n0 + (wn << 5) + (ni << 3) + (tg << 1);
            *(float2*)&C[(size_t)row * DD + col] =
                make_float2(acc[mi][ni][0], acc[mi][ni][1]);
            *(float2*)&C[(size_t)(row + 8) * DD + col] =
                make_float2(acc[mi][ni][2], acc[mi][ni][3]);
        }
    }
}
#define GEMM_SMEM_B ((2 * 128 * GST + 2 * 64 * GST) * 4)   // 55296

// =====================================================================
// Fused attention, mma.sync tf32 (unchanged, known-good from R4/R7)
// =====================================================================
#define KS_STRIDE 68
#define PS_STRIDE 132
#define SM_KS 0
#define SM_VS (128*KS_STRIDE)
#define SM_PS (2*128*KS_STRIDE)
#define SM_FLOATS (2*128*KS_STRIDE + 128*PS_STRIDE)
#define SMEM_TOTAL_B (SM_FLOATS*4)

__global__ __launch_bounds__(256, 1) void attn_mma(float* __restrict__ attn_out)
{
    extern __shared__ float sm[];
    float* KS = sm + SM_KS;
    float* VS = sm + SM_VS;
    float* PS = sm + SM_PS;

    const int tid  = threadIdx.x;
    const int wid  = tid >> 5;
    const int lane = tid & 31;
    const int g  = lane >> 2;
    const int tg = lane & 3;
    const int m0 = wid << 4;

    const int s0 = blockIdx.x << 7;
    const int b  = blockIdx.y;
    const int h  = blockIdx.z;

    const float* qg = g_q + (size_t)b * SS * DD + h * DHD;
    const float* kg = g_k + (size_t)b * SS * DD + h * DHD;
    const float* vg = g_v + (size_t)b * SS * DD + h * DHD;

    #pragma unroll
    for (int i = 0; i < 8; i++) {
        const int idx = tid + (i << 8);
        const int row = idx >> 4;
        const int e0  = (idx & 15) << 2;
        float4 v = *(const float4*)&qg[(size_t)(s0 + row) * DD + e0];
        uint4 t;
        t.x = f2tf32(v.x); t.y = f2tf32(v.y);
        t.z = f2tf32(v.z); t.w = f2tf32(v.w);
        *(uint4*)&VS[row * KS_STRIDE + e0] = t;
    }
    __syncthreads();

    uint32_t qa[8][4];
    #pragma unroll
    for (int ks = 0; ks < 8; ks++) {
        const int base = (m0 + g) * KS_STRIDE + (ks << 3) + tg;
        qa[ks][0] = __float_as_uint(VS[base]);
        qa[ks][1] = __float_as_uint(VS[base + 8 * KS_STRIDE]);
        qa[ks][2] = __float_as_uint(VS[base + 4]);
        qa[ks][3] = __float_as_uint(VS[base + 8 * KS_STRIDE + 4]);
    }
    __syncthreads();

    float rlo = 0.f, rhi = 0.f;
    for (int t0i = 0; t0i < 16; t0i++) {
        const int t0 = t0i << 7;
        #pragma unroll
        for (int i = 0; i < 8; i++) {
            const int idx = tid + (i << 8);
            const int row = idx >> 4;
            const int e0  = (idx & 15) << 2;
            float4 v = *(const float4*)&kg[(size_t)(t0 + row) * DD + e0];
            uint4 t;
            t.x = f2tf32(v.x); t.y = f2tf32(v.y);
            t.z = f2tf32(v.z); t.w = f2tf32(v.w);
            *(uint4*)&KS[row * KS_STRIDE + e0] = t;
        }
        __syncthreads();

        #pragma unroll
        for (int nt = 0; nt < 16; nt++) {
            float c[4] = {0.f, 0.f, 0.f, 0.f};
            #pragma unroll
            for (int ks = 0; ks < 8; ks++) {
                const int kb = (((nt << 3) + g) * KS_STRIDE) + (ks << 3) + tg;
                mma_tf32(c, qa[ks],
                         __float_as_uint(KS[kb]),
                         __float_as_uint(KS[kb + 4]));
            }
            rlo += __expf(c[0] * 0.125f) + __expf(c[1] * 0.125f);
            rhi += __expf(c[2] * 0.125f) + __expf(c[3] * 0.125f);
        }
        __syncthreads();
    }
    rlo += __shfl_xor_sync(0xffffffffu, rlo, 1);
    rlo += __shfl_xor_sync(0xffffffffu, rlo, 2);
    rhi += __shfl_xor_sync(0xffffffffu, rhi, 1);
    rhi += __shfl_xor_sync(0xffffffffu, rhi, 2);
    const float inv_lo = 1.0f / rlo;
    const float inv_hi = 1.0f / rhi;

    float oc[8][4];
    #pragma unroll
    for (int nt = 0; nt < 8; nt++)
        #pragma unroll
        for (int j = 0; j < 4; j++) oc[nt][j] = 0.f;

    for (int t0i = 0; t0i < 16; t0i++) {
        const int t0 = t0i << 7;
        #pragma unroll
        for (int i = 0; i < 8; i++) {
            const int idx = tid + (i << 8);
            const int row = idx >> 4;
            const int e0  = (idx & 15) << 2;
            float4 v = *(const float4*)&kg[(size_t)(t0 + row) * DD + e0];
            uint4 t;
            t.x = f2tf32(v.x); t.y = f2tf32(v.y);
            t.z = f2tf32(v.z); t.w = f2tf32(v.w);
            *(uint4*)&KS[row * KS_STRIDE + e0] = t;
        }
        #pragma unroll
        for (int i = 0; i < 8; i++) {
            const int idx = tid + (i << 8);
            const int row = idx >> 4;
            const int e0  = (idx & 15) << 2;
            float4 v = *(const float4*)&vg[(size_t)(t0 + row) * DD + e0];
            uint4 t;
            t.x = f2tf32(v.x); t.y = f2tf32(v.y);
            t.z = f2tf32(v.z); t.w = f2tf32(v.w);
            *(uint4*)&VS[row * KS_STRIDE + e0] = t;
        }
        __syncthreads();

        #pragma unroll
        for (int nt = 0; nt < 16; nt++) {
            float c[4] = {0.f, 0.f, 0.f, 0.f};
            #pragma unroll
            for (int ks = 0; ks < 8; ks++) {
                const int kb = (((nt << 3) + g) * KS_STRIDE) + (ks << 3) + tg;
                mma_tf32(c, qa[ks],
                         __float_as_uint(KS[kb]),
                         __float_as_uint(KS[kb + 4]));
            }
            const int row = m0 + g;
            const int col = (nt << 3) + (tg << 1);
            *(float2*)&PS[row * PS_STRIDE + col] =
                make_float2(__expf(c[0] * 0.125f) * inv_lo,
                            __expf(c[1] * 0.125f) * inv_lo);
            *(float2*)&PS[(row + 8) * PS_STRIDE + col] =
                make_float2(__expf(c[2] * 0.125f) * inv_hi,
                            __expf(c[3] * 0.125f) * inv_hi);
        }
        __syncthreads();

        #pragma unroll
        for (int ks = 0; ks < 16; ks++) {
            uint32_t a[4];
            const int base = (m0 + g) * PS_STRIDE + (ks << 3) + tg;
            a[0] = __float_as_uint(PS[base]);
            a[1] = __float_as_uint(PS[base + 8 * PS_STRIDE]);
            a[2] = __float_as_uint(PS[base + 4]);
            a[3] = __float_as_uint(PS[base + 8 * PS_STRIDE + 4]);
            #pragma unroll
            for (int nt = 0; nt < 8; nt++) {
                const int vb0 = ((ks << 3) + tg) * KS_STRIDE + (nt << 3) + g;
                mma_tf32(oc[nt], a,
                         __float_as_uint(VS[vb0]),
                         __float_as_uint(VS[vb0 + 4 * KS_STRIDE]));
            }
        }

        if (attn_out) {
            const size_t gbase = ((size_t)(h * BB + b) * SS + s0) * SS + t0;
            #pragma unroll
            for (int i = 0; i < 16; i++) {
                const int lin = tid + (i << 8);
                const int row = lin >> 5;
                const int c4  = (lin & 31) << 2;
                float4 pv = *(const float4*)&PS[row * PS_STRIDE + c4];
                *(float4*)&attn_out[gbase + (size_t)row * SS + c4] = pv;
            }
        }
        __syncthreads();
    }

    {
        const size_t row = (size_t)(b * SS + s0 + m0 + g);
        #pragma unroll
        for (int nt = 0; nt < 8; nt++) {
            const int col = h * DHD + (nt << 3) + (tg << 1);
            *(float2*)&g_concat[row * DD + col] =
                make_float2(oc[nt][0], oc[nt][1]);
            *(float2*)&g_concat[(row + 8) * DD + col] =
                make_float2(oc[nt][2], oc[nt][3]);
        }
    }
}

// =====================================================================
extern "C" void kernel_launch(void* const* d_in, const int* in_sizes, int n_in,
                              void* d_out, int out_size)
{
    const float* query = (const float*)d_in[0];
    const float* key   = (const float*)d_in[1];
    const float* value = (const float*)d_in[2];
    const float* Wq    = (const float*)d_in[3];
    const float* Wk    = (const float*)d_in[4];
    const float* Wv    = (const float*)d_in[5];
    const float* Wo    = (const float*)d_in[6];
    float* out = (float*)d_out;

    float* attn_ptr = nullptr;
    if ((long long)out_size >= (long long)OUT_ELEMS + ATTN_ELEMS)
        attn_ptr = out + OUT_ELEMS;

    // 0) one-shot bf16 hi/lo splits
    split_in<<<NROWS * K2 / 256, 256>>>(query, 0);
    split_in<<<NROWS * K2 / 256, 256>>>(key,   1);
    split_in<<<NROWS * K2 / 256, 256>>>(value, 2);
    split_w<<<DD * K2 / 256, 256>>>(Wq, 0);
    split_w<<<DD * K2 / 256, 256>>>(Wk, 1);
    split_w<<<DD * K2 / 256, 256>>>(Wv, 2);
    split_wo<<<DD * K2 / 256, 256>>>(Wo);

    // 1) projections (3xBF16 tensor cores): q,k,v in one grid
    cudaFuncSetAttribute(gemm_tc, cudaFuncAttributeMaxDynamicSharedMemorySize,
                         GEMM_SMEM_B);
    gemm_tc<<<dim3(NROWS / 128, DD / 64, 3), 256, GEMM_SMEM_B>>>(0, nullptr);

    // 2) fused attention (mma.sync tf32)
    cudaFuncSetAttribute(attn_mma, cudaFuncAttributeMaxDynamicSharedMemorySize,
                         SMEM_TOTAL_B);
    attn_mma<<<dim3(SS / 128, BB, HH), 256, SMEM_TOTAL_B>>>(attn_ptr);

    // 3) output projection (3xBF16 tensor cores)
    split_cat<<<NROWS * K2 / 256, 256>>>();
    gemm_tc<<<dim3(NROWS / 128, DD / 64, 1), 256, GEMM_SMEM_B>>>(3, out);
}

// round 16
// speedup vs baseline: 1.0038x; 1.0038x over previous
#include <cuda_runtime.h>
#include <cuda_bf16.h>
#include <cstdint>

#define BB 2
#define SS 2048
#define DD 1024
#define HH 16
#define DHD 64
#define NROWS (BB*SS)          // 4096
#define OUT_ELEMS (BB*SS*DD)   // 4194304
#define ATTN_ELEMS ((long long)HH*BB*SS*SS) // 134217728
#define K2 512                  // DD/2 packed bf16x2 words per row

// ---------------- scratch (device globals: allowed) ----------------
__device__ float g_q[NROWS * DD];
__device__ float g_k[NROWS * DD];
__device__ float g_v[NROWS * DD];
__device__ float g_concat[NROWS * DD];

// bf16 hi/lo split operands (packed pairs along k)
__device__ uint32_t g_ah[3][NROWS * K2];   // query/key/value inputs
__device__ uint32_t g_al[3][NROWS * K2];
__device__ uint32_t g_bh[4][DD * K2];      // Wq,Wk,Wv,Wo (n-major [n][k2])
__device__ uint32_t g_bl[4][DD * K2];
__device__ uint32_t g_ch[NROWS * K2];      // concat split
__device__ uint32_t g_cl[NROWS * K2];

// =====================================================================
// mma.sync helpers (sm_80+ PTX; compiles on plain sm_103 target)
// =====================================================================
__device__ __forceinline__ uint32_t f2tf32(float f) {
    uint32_t r;
    asm("cvt.rn.tf32.f32 %0, %1;" : "=r"(r) : "f"(f));
    return r;
}
__device__ __forceinline__ void mma_tf32(float c[4], const uint32_t a[4],
                                         uint32_t b0, uint32_t b1) {
    asm volatile(
        "mma.sync.aligned.m16n8k8.row.col.f32.tf32.tf32.f32 "
        "{%0,%1,%2,%3}, {%4,%5,%6,%7}, {%8,%9}, {%0,%1,%2,%3};"
        : "+f"(c[0]), "+f"(c[1]), "+f"(c[2]), "+f"(c[3])
        : "r"(a[0]), "r"(a[1]), "r"(a[2]), "r"(a[3]), "r"(b0), "r"(b1));
}
__device__ __forceinline__ void mma_bf16(float c[4], const uint32_t a[4],
                                         uint32_t b0, uint32_t b1) {
    asm volatile(
        "mma.sync.aligned.m16n8k16.row.col.f32.bf16.bf16.f32 "
        "{%0,%1,%2,%3}, {%4,%5,%6,%7}, {%8,%9}, {%0,%1,%2,%3};"
        : "+f"(c[0]), "+f"(c[1]), "+f"(c[2]), "+f"(c[3])
        : "r"(a[0]), "r"(a[1]), "r"(a[2]), "r"(a[3]), "r"(b0), "r"(b1));
}

// split a float2 into packed bf16x2 hi + residual lo
__device__ __forceinline__ void split2(float2 v, uint32_t& hi, uint32_t& lo) {
    __nv_bfloat162 h = __floats2bfloat162_rn(v.x, v.y);
    float r0 = v.x - __low2float(h);
    float r1 = v.y - __high2float(h);
    __nv_bfloat162 l = __floats2bfloat162_rn(r0, r1);
    hi = *(uint32_t*)&h;
    lo = *(uint32_t*)&l;
}

// =====================================================================
// Split kernels (one-shot fp32 -> bf16 hi/lo packed pairs)
// =====================================================================
__global__ void split_in(const float* __restrict__ src, int which) {
    const int idx = blockIdx.x * 256 + threadIdx.x;           // over NROWS*K2
    float2 v = *(const float2*)&src[(size_t)idx * 2];
    split2(v, g_ah[which][idx], g_al[which][idx]);
}
__global__ void split_w(const float* __restrict__ W, int which) {
    const int idx = blockIdx.x * 256 + threadIdx.x;           // over DD*K2
    const int e  = idx & 63;
    const int k2 = (idx >> 6) & 511;
    const int h  = idx >> 15;
    float f0 = W[(size_t)((h << 10) + (k2 << 1)) * 64 + e];
    float f1 = W[(size_t)((h << 10) + (k2 << 1) + 1) * 64 + e];
    uint32_t hi, lo;
    split2(make_float2(f0, f1), hi, lo);
    const int n = (h << 6) + e;
    g_bh[which][(size_t)n * K2 + k2] = hi;
    g_bl[which][(size_t)n * K2 + k2] = lo;
}
__global__ void split_wo(const float* __restrict__ Wo) {
    const int idx = blockIdx.x * 256 + threadIdx.x;           // over DD*K2
    const int n = idx >> 9, k2 = idx & 511;
    float2 v = *(const float2*)&Wo[(size_t)n * DD + (k2 << 1)];
    split2(v, g_bh[3][idx], g_bl[3][idx]);
}
__global__ void split_cat() {
    const int idx = blockIdx.x * 256 + threadIdx.x;           // over NROWS*K2
    float2 v = *(const float2*)&g_concat[(size_t)idx * 2];
    split2(v, g_ch[idx], g_cl[idx]);
}

// =====================================================================
// 3xBF16 tensor-core GEMM: C[4096 x 1024] = A[4096 x 1024] * B^T-ish
// mode 0..2: proj q/k/v (C = g_q/g_k/g_v); mode 3: out (C = outp)
// Tile 128x64, BK=64 (32 k2), 8 warps as 4m x 2n (warp m32 x n32).
// =====================================================================
#define GST 36   // smem row stride in u32 (32 k2 padded: conflict-free frags)

__global__ __launch_bounds__(256, 2) void gemm_tc(int base_mode,
                                                  float* __restrict__ outp)
{
    extern __shared__ uint32_t smu[];
    uint32_t* Ah = smu;                     // 128*36
    uint32_t* Al = smu + 128 * GST;
    uint32_t* Bh = smu + 2 * 128 * GST;     // 64*36
    uint32_t* Bl = smu + 2 * 128 * GST + 64 * GST;

    const int mode = base_mode + blockIdx.z;
    const uint32_t *a_hi, *a_lo, *b_hi, *b_lo;
    float* C;
    if (mode < 3) {
        a_hi = g_ah[mode]; a_lo = g_al[mode];
        b_hi = g_bh[mode]; b_lo = g_bl[mode];
        C = (mode == 0) ? g_q : (mode == 1) ? g_k : g_v;
    } else {
        a_hi = g_ch; a_lo = g_cl;
        b_hi = g_bh[3]; b_lo = g_bl[3];
        C = outp;
    }

    const int tid  = threadIdx.x;
    const int wid  = tid >> 5, lane = tid & 31;
    const int g    = lane >> 2, tg = lane & 3;
    const int wm   = wid >> 1, wn = wid & 1;
    const int row0 = blockIdx.x << 7;
    const int n0   = blockIdx.y << 6;

    float acc[2][4][4] = {};

    for (int kt = 0; kt < 16; kt++) {
        const int k2o = kt << 5;
        #pragma unroll
        for (int i = 0; i < 4; i++) {                     // A: 128x32 u32
            const int idx = tid + (i << 8);
            const int r = idx >> 3, q = (idx & 7) << 2;
            *(uint4*)&Ah[r * GST + q] =
                *(const uint4*)&a_hi[(size_t)(row0 + r) * K2 + k2o + q];
            *(uint4*)&Al[r * GST + q] =
                *(const uint4*)&a_lo[(size_t)(row0 + r) * K2 + k2o + q];
        }
        #pragma unroll
        for (int i = 0; i < 2; i++) {                     // B: 64x32 u32
            const int idx = tid + (i << 8);
            const int r = idx >> 3, q = (idx & 7) << 2;
            *(uint4*)&Bh[r * GST + q] =
                *(const uint4*)&b_hi[(size_t)(n0 + r) * K2 + k2o + q];
            *(uint4*)&Bl[r * GST + q] =
                *(const uint4*)&b_lo[(size_t)(n0 + r) * K2 + k2o + q];
        }
        __syncthreads();

        #pragma unroll
        for (int s = 0; s < 4; s++) {                     // 4 x k16 steps
            const int ko = s << 3;
            uint32_t ah[2][4], al[2][4];
            #pragma unroll
            for (int mi = 0; mi < 2; mi++) {
                const int ar = ((wm << 5) + (mi << 4) + g) * GST + ko + tg;
                ah[mi][0] = Ah[ar];            ah[mi][1] = Ah[ar + 8 * GST];
                ah[mi][2] = Ah[ar + 4];        ah[mi][3] = Ah[ar + 8 * GST + 4];
                al[mi][0] = Al[ar];            al[mi][1] = Al[ar + 8 * GST];
                al[mi][2] = Al[ar + 4];        al[mi][3] = Al[ar + 8 * GST + 4];
            }
            #pragma unroll
            for (int ni = 0; ni < 4; ni++) {
                const int br = ((wn << 5) + (ni << 3) + g) * GST + ko + tg;
                const uint32_t bh0 = Bh[br], bh1 = Bh[br + 4];
                const uint32_t bl0 = Bl[br], bl1 = Bl[br + 4];
                #pragma unroll
                for (int mi = 0; mi < 2; mi++) {
                    mma_bf16(acc[mi][ni], ah[mi], bh0, bh1);
                    mma_bf16(acc[mi][ni], ah[mi], bl0, bl1);
                    mma_bf16(acc[mi][ni], al[mi], bh0, bh1);
                }
            }
        }
        __syncthreads();
    }

    #pragma unroll
    for (int mi = 0; mi < 2; mi++) {
        const int row = row0 + (wm << 5) + (mi << 4) + g;
        #pragma unroll
        for (int ni = 0; ni < 4; ni++) {
            const int col = n0 + (wn << 5) + (ni << 3) + (tg << 1);
            *(float2*)&C[(size_t)row * DD + col] =
                make_float2(acc[mi][ni][0], acc[mi][ni][1]);
            *(float2*)&C[(size_t)(row + 8) * DD + col] =
                make_float2(acc[mi][ni][2], acc[mi][ni][3]);
        }
    }
}
#define GEMM_SMEM_B ((2 * 128 * GST + 2 * 64 * GST) * 4)   // 55296

// =====================================================================
// Fused attention, mma.sync tf32 (unchanged, known-good from R4/R7)
// =====================================================================
#define KS_STRIDE 68
#define PS_STRIDE 132
#define SM_KS 0
#define SM_VS (128*KS_STRIDE)
#define SM_PS (2*128*KS_STRIDE)
#define SM_FLOATS (2*128*KS_STRIDE + 128*PS_STRIDE)
#define SMEM_TOTAL_B (SM_FLOATS*4)

__global__ __launch_bounds__(256, 1) void attn_mma(float* __restrict__ attn_out)
{
    extern __shared__ float sm[];
    float* KS = sm + SM_KS;
    float* VS = sm + SM_VS;
    float* PS = sm + SM_PS;

    const int tid  = threadIdx.x;
    const int wid  = tid >> 5;
    const int lane = tid & 31;
    const int g  = lane >> 2;
    const int tg = lane & 3;
    const int m0 = wid << 4;

    const int s0 = blockIdx.x << 7;
    const int b  = blockIdx.y;
    const int h  = blockIdx.z;

    const float* qg = g_q + (size_t)b * SS * DD + h * DHD;
    const float* kg = g_k + (size_t)b * SS * DD + h * DHD;
    const float* vg = g_v + (size_t)b * SS * DD + h * DHD;

    #pragma unroll
    for (int i = 0; i < 8; i++) {
        const int idx = tid + (i << 8);
        const int row = idx >> 4;
        const int e0  = (idx & 15) << 2;
        float4 v = *(const float4*)&qg[(size_t)(s0 + row) * DD + e0];
        uint4 t;
        t.x = f2tf32(v.x); t.y = f2tf32(v.y);
        t.z = f2tf32(v.z); t.w = f2tf32(v.w);
        *(uint4*)&VS[row * KS_STRIDE + e0] = t;
    }
    __syncthreads();

    uint32_t qa[8][4];
    #pragma unroll
    for (int ks = 0; ks < 8; ks++) {
        const int base = (m0 + g) * KS_STRIDE + (ks << 3) + tg;
        qa[ks][0] = __float_as_uint(VS[base]);
        qa[ks][1] = __float_as_uint(VS[base + 8 * KS_STRIDE]);
        qa[ks][2] = __float_as_uint(VS[base + 4]);
        qa[ks][3] = __float_as_uint(VS[base + 8 * KS_STRIDE + 4]);
    }
    __syncthreads();

    float rlo = 0.f, rhi = 0.f;
    for (int t0i = 0; t0i < 16; t0i++) {
        const int t0 = t0i << 7;
        #pragma unroll
        for (int i = 0; i < 8; i++) {
            const int idx = tid + (i << 8);
            const int row = idx >> 4;
            const int e0  = (idx & 15) << 2;
            float4 v = *(const float4*)&kg[(size_t)(t0 + row) * DD + e0];
            uint4 t;
            t.x = f2tf32(v.x); t.y = f2tf32(v.y);
            t.z = f2tf32(v.z); t.w = f2tf32(v.w);
            *(uint4*)&KS[row * KS_STRIDE + e0] = t;
        }
        __syncthreads();

        #pragma unroll
        for (int nt = 0; nt < 16; nt++) {
            float c[4] = {0.f, 0.f, 0.f, 0.f};
            #pragma unroll
            for (int ks = 0; ks < 8; ks++) {
                const int kb = (((nt << 3) + g) * KS_STRIDE) + (ks << 3) + tg;
                mma_tf32(c, qa[ks],
                         __float_as_uint(KS[kb]),
                         __float_as_uint(KS[kb + 4]));
            }
            rlo += __expf(c[0] * 0.125f) + __expf(c[1] * 0.125f);
            rhi += __expf(c[2] * 0.125f) + __expf(c[3] * 0.125f);
        }
        __syncthreads();
    }
    rlo += __shfl_xor_sync(0xffffffffu, rlo, 1);
    rlo += __shfl_xor_sync(0xffffffffu, rlo, 2);
    rhi += __shfl_xor_sync(0xffffffffu, rhi, 1);
    rhi += __shfl_xor_sync(0xffffffffu, rhi, 2);
    const float inv_lo = 1.0f / rlo;
    const float inv_hi = 1.0f / rhi;

    float oc[8][4];
    #pragma unroll
    for (int nt = 0; nt < 8; nt++)
        #pragma unroll
        for (int j = 0; j < 4; j++) oc[nt][j] = 0.f;

    for (int t0i = 0; t0i < 16; t0i++) {
        const int t0 = t0i << 7;
        #pragma unroll
        for (int i = 0; i < 8; i++) {
            const int idx = tid + (i << 8);
            const int row = idx >> 4;
            const int e0  = (idx & 15) << 2;
            float4 v = *(const float4*)&kg[(size_t)(t0 + row) * DD + e0];
            uint4 t;
            t.x = f2tf32(v.x); t.y = f2tf32(v.y);
            t.z = f2tf32(v.z); t.w = f2tf32(v.w);
            *(uint4*)&KS[row * KS_STRIDE + e0] = t;
        }
        #pragma unroll
        for (int i = 0; i < 8; i++) {
            const int idx = tid + (i << 8);
            const int row = idx >> 4;
            const int e0  = (idx & 15) << 2;
            float4 v = *(const float4*)&vg[(size_t)(t0 + row) * DD + e0];
            uint4 t;
            t.x = f2tf32(v.x); t.y = f2tf32(v.y);
            t.z = f2tf32(v.z); t.w = f2tf32(v.w);
            *(uint4*)&VS[row * KS_STRIDE + e0] = t;
        }
        __syncthreads();

        #pragma unroll
        for (int nt = 0; nt < 16; nt++) {
            float c[4] = {0.f, 0.f, 0.f, 0.f};
            #pragma unroll
            for (int ks = 0; ks < 8; ks++) {
                const int kb = (((nt << 3) + g) * KS_STRIDE) + (ks << 3) + tg;
                mma_tf32(c, qa[ks],
                         __float_as_uint(KS[kb]),
                         __float_as_uint(KS[kb + 4]));
            }
            const int row = m0 + g;
            const int col = (nt << 3) + (tg << 1);
            *(float2*)&PS[row * PS_STRIDE + col] =
                make_float2(__expf(c[0] * 0.125f) * inv_lo,
                            __expf(c[1] * 0.125f) * inv_lo);
            *(float2*)&PS[(row + 8) * PS_STRIDE + col] =
                make_float2(__expf(c[2] * 0.125f) * inv_hi,
                            __expf(c[3] * 0.125f) * inv_hi);
        }
        __syncthreads();

        #pragma unroll
        for (int ks = 0; ks < 16; ks++) {
            uint32_t a[4];
            const int base = (m0 + g) * PS_STRIDE + (ks << 3) + tg;
            a[0] = __float_as_uint(PS[base]);
            a[1] = __float_as_uint(PS[base + 8 * PS_STRIDE]);
            a[2] = __float_as_uint(PS[base + 4]);
            a[3] = __float_as_uint(PS[base + 8 * PS_STRIDE + 4]);
            #pragma unroll
            for (int nt = 0; nt < 8; nt++) {
                const int vb0 = ((ks << 3) + tg) * KS_STRIDE + (nt << 3) + g;
                mma_tf32(oc[nt], a,
                         __float_as_uint(VS[vb0]),
                         __float_as_uint(VS[vb0 + 4 * KS_STRIDE]));
            }
        }

        if (attn_out) {
            const size_t gbase = ((size_t)(h * BB + b) * SS + s0) * SS + t0;
            #pragma unroll
            for (int i = 0; i < 16; i++) {
                const int lin = tid + (i << 8);
                const int row = lin >> 5;
                const int c4  = (lin & 31) << 2;
                float4 pv = *(const float4*)&PS[row * PS_STRIDE + c4];
                *(float4*)&attn_out[gbase + (size_t)row * SS + c4] = pv;
            }
        }
        __syncthreads();
    }

    {
        const size_t row = (size_t)(b * SS + s0 + m0 + g);
        #pragma unroll
        for (int nt = 0; nt < 8; nt++) {
            const int col = h * DHD + (nt << 3) + (tg << 1);
            *(float2*)&g_concat[row * DD + col] =
                make_float2(oc[nt][0], oc[nt][1]);
            *(float2*)&g_concat[(row + 8) * DD + col] =
                make_float2(oc[nt][2], oc[nt][3]);
        }
    }
}

// =====================================================================
extern "C" void kernel_launch(void* const* d_in, const int* in_sizes, int n_in,
                              void* d_out, int out_size)
{
    const float* query = (const float*)d_in[0];
    const float* key   = (const float*)d_in[1];
    const float* value = (const float*)d_in[2];
    const float* Wq    = (const float*)d_in[3];
    const float* Wk    = (const float*)d_in[4];
    const float* Wv    = (const float*)d_in[5];
    const float* Wo    = (const float*)d_in[6];
    float* out = (float*)d_out;

    float* attn_ptr = nullptr;
    if ((long long)out_size >= (long long)OUT_ELEMS + ATTN_ELEMS)
        attn_ptr = out + OUT_ELEMS;

    // 0) one-shot bf16 hi/lo splits
    split_in<<<NROWS * K2 / 256, 256>>>(query, 0);
    split_in<<<NROWS * K2 / 256, 256>>>(key,   1);
    split_in<<<NROWS * K2 / 256, 256>>>(value, 2);
    split_w<<<DD * K2 / 256, 256>>>(Wq, 0);
    split_w<<<DD * K2 / 256, 256>>>(Wk, 1);
    split_w<<<DD * K2 / 256, 256>>>(Wv, 2);
    split_wo<<<DD * K2 / 256, 256>>>(Wo);

    // 1) projections (3xBF16 tensor cores): q,k,v in one grid
    cudaFuncSetAttribute(gemm_tc, cudaFuncAttributeMaxDynamicSharedMemorySize,
                         GEMM_SMEM_B);
    gemm_tc<<<dim3(NROWS / 128, DD / 64, 3), 256, GEMM_SMEM_B>>>(0, nullptr);

    // 2) fused attention (mma.sync tf32)
    cudaFuncSetAttribute(attn_mma, cudaFuncAttributeMaxDynamicSharedMemorySize,
                         SMEM_TOTAL_B);
    attn_mma<<<dim3(SS / 128, BB, HH), 256, SMEM_TOTAL_B>>>(attn_ptr);

    // 3) output projection (3xBF16 tensor cores)
    split_cat<<<NROWS * K2 / 256, 256>>>();
    gemm_tc<<<dim3(NROWS / 128, DD / 64, 1), 256, GEMM_SMEM_B>>>(3, out);
}